// round 11
// baseline (speedup 1.0000x reference)
#include <cuda_runtime.h>
#include <cstdint>

#define DIMN 384
#define NP 192                    // uint2 per packed B row (full K)
#define PSC 100                   // B chunk smem pitch in uint2 (96 data + 4 pad)
#define A4_CNT 3072               // uint4 per 32-row A block (full K)
#define A4_CHUNK 1536             // uint4 per chunk (K=192)
#define SMEM_A4C (A4_CHUNK * 16)  // 24576 B
#define SMEM_BC  (32 * PSC * 8)   // 25600 B
#define SMEM_GEMM (SMEM_A4C + SMEM_BC)  // 50176 -> 3 CTAs/SM

// Scratch (no cudaMalloc allowed)
// A operands: interleaved uint4 layout [rowblock][ks][p][t4]:
//   p (0..15): rows (32rb + (p&7) + (p>>3)*16, +8)
//   uint4 = {A[r][8ks+t4], A[r][8ks+t4+4], A[r+8][8ks+t4], A[r+8][8ks+t4+4]}
__device__ __align__(16) uint4 g_v1p4[32 * A4_CNT];   // packed v1
__device__ __align__(16) uint4 g_tp4[32 * A4_CNT];    // packed t (gemm0 out)
// B operands: pair layout [n][s]: uint2 = {B[n][8(s>>2)+(s&3)], ... +4}
__device__ __align__(16) uint2 g_lwp[DIMN * NP];      // packed lin_W
__device__ __align__(16) uint2 g_Ptp[DIMN * NP];      // packed rw[i]*P[i][j], row j
__device__ float g_cbar[DIMN];

__device__ __forceinline__ uint32_t f2tf32(float x) {
    uint32_t y; asm("cvt.rna.tf32.f32 %0, %1;" : "=r"(y) : "f"(x)); return y;
}
__device__ __forceinline__ uint32_t smem_u32(const void* p) {
    uint32_t a;
    asm("{ .reg .u64 t; cvta.to.shared.u64 t, %1; cvt.u32.u64 %0, t; }" : "=r"(a) : "l"(p));
    return a;
}
__device__ __forceinline__ void cp16(uint32_t dst, const void* src) {
    asm volatile("cp.async.cg.shared.global [%0], [%1], 16;" :: "r"(dst), "l"(src) : "memory");
}
__device__ __forceinline__ void cp_wait_all() {
    asm volatile("cp.async.commit_group;" ::: "memory");
    asm volatile("cp.async.wait_group 0;" ::: "memory");
}
__device__ __forceinline__ void mma8(float* d, const uint32_t* a, uint32_t b0, uint32_t b1) {
    asm("mma.sync.aligned.m16n8k8.row.col.f32.tf32.tf32.f32 "
        "{%0,%1,%2,%3}, {%4,%5,%6,%7}, {%8,%9}, {%0,%1,%2,%3};"
        : "+f"(d[0]), "+f"(d[1]), "+f"(d[2]), "+f"(d[3])
        : "r"(a[0]), "r"(a[1]), "r"(a[2]), "r"(a[3]), "r"(b0), "r"(b1));
}

// ---------------------------------------------------------------------------
// cvt_pack: blocks [0,384): v1 -> g_v1p4 (interleaved uint4).
//           blocks [384,672): lin_W -> g_lwp (uint2 pairs). Zeroes cbar.
// ---------------------------------------------------------------------------
__global__ __launch_bounds__(256)
void cvt_pack_kernel(const float* __restrict__ v1, const float* __restrict__ linW) {
    const int bid = blockIdx.x, tid = threadIdx.x;
    if (bid < 384) {
        const int idx = bid * 256 + tid;
        const int rb = idx / A4_CNT, rem = idx - rb * A4_CNT;
        const int ks = rem >> 6, p = (rem >> 2) & 15, t4 = rem & 3;
        const int r = rb * 32 + (p & 7) + ((p >> 3) << 4);
        const int k0 = ks * 8 + t4;
        const float* s0 = v1 + r * DIMN + k0;
        const float* s1 = s0 + 8 * DIMN;
        g_v1p4[idx] = make_uint4(f2tf32(s0[0]), f2tf32(s0[4]),
                                 f2tf32(s1[0]), f2tf32(s1[4]));
        if (idx < DIMN) g_cbar[idx] = 0.f;
    } else {
        const int idx = (bid - 384) * 256 + tid;
        const int row = idx / NP, s = idx - row * NP;
        const int k0 = (s >> 2) * 8 + (s & 3);
        const float* src = linW + row * DIMN + k0;
        g_lwp[idx] = make_uint2(f2tf32(src[0]), f2tf32(src[4]));
    }
}

// ---------------------------------------------------------------------------
// prep: per 32x32 tile: p = prod(1-W_k), c = chain bias.
// g_Ptp[j][pairs over i] = rw[i]*p (transposed+packed); cbar[j] += rw[i]*c.
// ---------------------------------------------------------------------------
__global__ __launch_bounds__(256)
void prep_kernel(const float* __restrict__ W, const float* __restrict__ Bb,
                 const float* __restrict__ rw, int nblocks) {
    __shared__ float pt[32][33];
    __shared__ float cp[32][33];
    const int tid = threadIdx.x;
    const int bi = blockIdx.x, bj = blockIdx.y;
    const int il = tid >> 3, j4 = (tid & 7) * 4;
    const int gi = bi * 32 + il, gj = bj * 32 + j4;

    float4 p = make_float4(1.f, 1.f, 1.f, 1.f);
    float4 c = make_float4(0.f, 0.f, 0.f, 0.f);
    for (int k = 0; k < nblocks; k++) {
        float4 w = *(const float4*)&W[(size_t)k * DIMN * DIMN + gi * DIMN + gj];
        float4 b = *(const float4*)&Bb[(size_t)k * DIMN * DIMN + gi * DIMN + gj];
        float4 om = make_float4(1.f - w.x, 1.f - w.y, 1.f - w.z, 1.f - w.w);
        p.x *= om.x; p.y *= om.y; p.z *= om.z; p.w *= om.w;
        c.x = c.x * om.x + b.x; c.y = c.y * om.y + b.y;
        c.z = c.z * om.z + b.z; c.w = c.w * om.w + b.w;
    }
    const float ri = rw[gi];
    pt[il][j4] = ri * p.x; pt[il][j4 + 1] = ri * p.y;
    pt[il][j4 + 2] = ri * p.z; pt[il][j4 + 3] = ri * p.w;
    cp[il][j4] = ri * c.x; cp[il][j4 + 1] = ri * c.y;
    cp[il][j4 + 2] = ri * c.z; cp[il][j4 + 3] = ri * c.w;
    __syncthreads();

    if (tid < 32) {
        float s = 0.f;
#pragma unroll
        for (int i = 0; i < 32; i++) s += cp[i][tid];
        atomicAdd(&g_cbar[bj * 32 + tid], s);
    }
#pragma unroll
    for (int q = tid; q < 512; q += 256) {
        int j = q >> 4, s = q & 15;
        int i0 = (s >> 2) * 8 + (s & 3);
        g_Ptp[(bj * 32 + j) * NP + bi * 16 + s] =
            make_uint2(f2tf32(pt[i0][j]), f2tf32(pt[i0 + 4][j]));
    }
}

// ---------------------------------------------------------------------------
// tf32 mma.sync GEMM, 32x32 tile / CTA, 256 thr / 8 warps = wn(2) x kh(4).
// K processed in 2 single-buffered chunks of 192 (smem halved -> 3 CTAs/SM).
// Per chunk each warp does 6 ks-steps: 2 LDS.128 (A) + 2 LDS.64 (B) -> 4 MMA.
// MODE 0: t = v2 .* (v1 @ rwP) - cbar   (out: g_tp4, interleaved packed)
// MODE 1: out = (t @ linW^T) + linb     (out: f32 d_out)
// ---------------------------------------------------------------------------
template <int MODE>
__global__ __launch_bounds__(256, 3)
void mma_gemm(const uint4* __restrict__ Ap4, const uint2* __restrict__ Bp,
              const float* __restrict__ v2, const float* __restrict__ cbar,
              const float* __restrict__ linb, void* __restrict__ OutV) {
    extern __shared__ __align__(16) char smc[];
    uint4* A4 = (uint4*)smc;
    uint2* Bs = (uint2*)(smc + SMEM_A4C);

    const int tid = threadIdx.x, lane = tid & 31, wid = tid >> 5;
    const int g = lane >> 2, t4 = lane & 3;
    const int wn = wid & 1, kh = wid >> 1;
    const int rb = blockIdx.y;
    const int m0 = rb * 32, n0 = blockIdx.x * 32;

    float acc[2][2][4] = {};

#pragma unroll
    for (int c = 0; c < 2; c++) {
        if (c) __syncthreads();           // all reads of previous chunk done
        // ---- load chunk c ----
        // A: 256 thr x 6 x 16B = 24576 B (full chunk, linear copy)
        // B: 8 thr/row x 6 x 16B = 768 B/row = 96 uint2 (full chunk row)
        {
            const uint32_t aB = smem_u32(A4);
            const char* aS = (const char*)(Ap4 + (size_t)rb * A4_CNT + c * A4_CHUNK);
#pragma unroll
            for (int j = 0; j < 6; j++) {
                int off = (tid + j * 256) * 16;
                cp16(aB + off, aS + off);
            }
            const int row = tid >> 3, c0 = tid & 7;
            const uint32_t bB = smem_u32(Bs) + row * (PSC * 8);
            const char* bS = (const char*)(Bp + (size_t)(n0 + row) * NP + c * 96);
#pragma unroll
            for (int j = 0; j < 6; j++) {
                int off = (c0 + 8 * j) * 16;
                cp16(bB + off, bS + off);
            }
        }
        cp_wait_all();
        __syncthreads();

        // ---- compute: 6 ks-steps on this warp's K-quarter of the chunk ----
        const uint4* aP = &A4[kh * 6 * 64 + g * 4 + t4];           // +32 mi=1, +64/ks
        const uint2* bP = &Bs[(wn * 16 + g) * PSC + kh * 24 + t4]; // +8*PSC nf=1, +4/ks

        uint4 qa[2][2]; uint2 qb[2][2];
        qa[0][0] = aP[0]; qa[0][1] = aP[32];
        qb[0][0] = bP[0]; qb[0][1] = bP[8 * PSC];
#pragma unroll
        for (int ks = 0; ks < 6; ks++) {
            const int cur = ks & 1, nxt = cur ^ 1;
            if (ks < 5) {
                const int oa = (ks + 1) * 64, ob = (ks + 1) * 4;
                qa[nxt][0] = aP[oa]; qa[nxt][1] = aP[oa + 32];
                qb[nxt][0] = bP[ob]; qb[nxt][1] = bP[8 * PSC + ob];
            }
#pragma unroll
            for (int mi = 0; mi < 2; mi++) {
                uint32_t a[4] = {qa[cur][mi].x, qa[cur][mi].z, qa[cur][mi].y, qa[cur][mi].w};
                mma8(acc[mi][0], a, qb[cur][0].x, qb[cur][0].y);
                mma8(acc[mi][1], a, qb[cur][1].x, qb[cur][1].y);
            }
        }
    }

    // ---- cross-quarter reduction via smem (reuse panel region) ----
    float* red = (float*)smc;        // 3 buffers of 32x34 floats (13KB)
    __syncthreads();
    if (kh > 0) {
        float* r = red + (kh - 1) * (32 * 34);
#pragma unroll
        for (int mi = 0; mi < 2; mi++) {
            const int rl = mi * 16 + g;
#pragma unroll
            for (int nf = 0; nf < 2; nf++) {
                const int c = wn * 16 + nf * 8 + 2 * t4;
                *(float2*)&r[rl * 34 + c]       = make_float2(acc[mi][nf][0], acc[mi][nf][1]);
                *(float2*)&r[(rl + 8) * 34 + c] = make_float2(acc[mi][nf][2], acc[mi][nf][3]);
            }
        }
    }
    __syncthreads();
    if (kh > 0) return;

#pragma unroll
    for (int b = 0; b < 3; b++) {
        const float* r = red + b * (32 * 34);
#pragma unroll
        for (int mi = 0; mi < 2; mi++) {
            const int rl = mi * 16 + g;
#pragma unroll
            for (int nf = 0; nf < 2; nf++) {
                const int c = wn * 16 + nf * 8 + 2 * t4;
                float2 p0 = *(const float2*)&r[rl * 34 + c];
                float2 p1 = *(const float2*)&r[(rl + 8) * 34 + c];
                acc[mi][nf][0] += p0.x; acc[mi][nf][1] += p0.y;
                acc[mi][nf][2] += p1.x; acc[mi][nf][3] += p1.y;
            }
        }
    }

    // ---- epilogue (kh==0 warps: wn 0,1 cover all 32 cols) ----
#pragma unroll
    for (int mi = 0; mi < 2; mi++) {
        const int r0 = m0 + mi * 16 + g, r1 = r0 + 8;
#pragma unroll
        for (int nf = 0; nf < 2; nf++) {
            const int C = n0 + wn * 16 + nf * 8 + 2 * t4;
            if (MODE == 0) {
                float2 cb = *(const float2*)&cbar[C];
                float2 va = *(const float2*)&v2[r0 * DIMN + C];
                float2 vb = *(const float2*)&v2[r1 * DIMN + C];
                float c0 = va.x * acc[mi][nf][0] - cb.x;
                float c1 = va.y * acc[mi][nf][1] - cb.y;
                float c2 = vb.x * acc[mi][nf][2] - cb.x;
                float c3 = vb.y * acc[mi][nf][3] - cb.y;
                float u0 = __shfl_down_sync(0xffffffffu, c0, 2);
                float u1 = __shfl_down_sync(0xffffffffu, c1, 2);
                float u2 = __shfl_down_sync(0xffffffffu, c2, 2);
                float u3 = __shfl_down_sync(0xffffffffu, c3, 2);
                if (t4 < 2) {
                    const int p = mi * 8 + g;
                    const int ks_g = (n0 + wn * 16 + nf * 8) >> 3;
                    size_t base = (size_t)rb * A4_CNT + ks_g * 64 + p * 4;
                    g_tp4[base + 2 * t4] =
                        make_uint4(f2tf32(c0), f2tf32(u0), f2tf32(c2), f2tf32(u2));
                    g_tp4[base + 2 * t4 + 1] =
                        make_uint4(f2tf32(c1), f2tf32(u1), f2tf32(c3), f2tf32(u3));
                }
            } else {
                float* Out = (float*)OutV;
                float2 lb = *(const float2*)&linb[C];
                *(float2*)&Out[r0 * DIMN + C] =
                    make_float2(acc[mi][nf][0] + lb.x, acc[mi][nf][1] + lb.y);
                *(float2*)&Out[r1 * DIMN + C] =
                    make_float2(acc[mi][nf][2] + lb.x, acc[mi][nf][3] + lb.y);
            }
        }
    }
}

// ---------------------------------------------------------------------------
// Launch. Inputs: v1, v2, block_W, block_b, row_weights, lin_W, lin_b
// ---------------------------------------------------------------------------
extern "C" void kernel_launch(void* const* d_in, const int* in_sizes, int n_in,
                              void* d_out, int out_size) {
    const float* v1   = (const float*)d_in[0];
    const float* v2   = (const float*)d_in[1];
    const float* bW   = (const float*)d_in[2];
    const float* bB   = (const float*)d_in[3];
    const float* rw   = (const float*)d_in[4];
    const float* linW = (const float*)d_in[5];
    const float* linb = (const float*)d_in[6];

    const int nblocks = in_sizes[2] / (DIMN * DIMN);
    const int batch   = in_sizes[0] / DIMN;

    uint4 *gv1p4, *gtp4; uint2 *glwp, *gPtp; float* gcb;
    cudaGetSymbolAddress((void**)&gv1p4, g_v1p4);
    cudaGetSymbolAddress((void**)&gtp4,  g_tp4);
    cudaGetSymbolAddress((void**)&glwp,  g_lwp);
    cudaGetSymbolAddress((void**)&gPtp,  g_Ptp);
    cudaGetSymbolAddress((void**)&gcb,   g_cbar);

    cudaFuncSetAttribute(mma_gemm<0>, cudaFuncAttributeMaxDynamicSharedMemorySize, SMEM_GEMM);
    cudaFuncSetAttribute(mma_gemm<1>, cudaFuncAttributeMaxDynamicSharedMemorySize, SMEM_GEMM);

    cvt_pack_kernel<<<672, 256>>>(v1, linW);
    prep_kernel<<<dim3(12, 12), 256>>>(bW, bB, rw, nblocks);
    dim3 grid(DIMN / 32, batch / 32);   // (12, 32) = 384 CTAs
    mma_gemm<0><<<grid, 256, SMEM_GEMM>>>(gv1p4, gPtp, v2, gcb, nullptr, nullptr);
    mma_gemm<1><<<grid, 256, SMEM_GEMM>>>(gtp4, glwp, nullptr, nullptr, linb, d_out);
}

// round 12
// speedup vs baseline: 1.0137x; 1.0137x over previous
#include <cuda_runtime.h>
#include <cstdint>

#define DIMN 384
#define NP 192                    // uint2 per packed B row (full K)
#define A4_CNT 3072               // uint4 per 32-row A block (full K)
// pipelined chunking: 4 chunks of K=96, 2-stage ring
#define A4_PER_CHUNK 768          // 12 ks * 16 p * 4 t4
#define ABYTES_C (A4_PER_CHUNK * 16)    // 12288
#define PSB 52                    // B chunk pitch in uint2 (48 data + 4 pad)
#define BBYTES_C (32 * PSB * 8)   // 13312
#define STAGE_B (ABYTES_C + BBYTES_C)   // 25600
#define SMEM_GEMM (2 * STAGE_B)   // 51200 -> 4 CTAs/SM

// Scratch (no cudaMalloc allowed)
// A operands: interleaved uint4 layout [rowblock][ks][p][t4]:
//   p (0..15): rows (32rb + (p&7) + (p>>3)*16, +8)
//   uint4 = {A[r][8ks+t4], A[r][8ks+t4+4], A[r+8][8ks+t4], A[r+8][8ks+t4+4]}
__device__ __align__(16) uint4 g_v1p4[32 * A4_CNT];   // packed v1
__device__ __align__(16) uint4 g_tp4[32 * A4_CNT];    // packed t (gemm0 out)
// B operands: pair layout [n][s]: uint2 = {B[n][8(s>>2)+(s&3)], ... +4}
__device__ __align__(16) uint2 g_lwp[DIMN * NP];      // packed lin_W
__device__ __align__(16) uint2 g_Ptp[DIMN * NP];      // packed rw[i]*P[i][j], row j
__device__ float g_cbar[DIMN];

__device__ __forceinline__ uint32_t f2tf32(float x) {
    uint32_t y; asm("cvt.rna.tf32.f32 %0, %1;" : "=r"(y) : "f"(x)); return y;
}
__device__ __forceinline__ uint32_t smem_u32(const void* p) {
    uint32_t a;
    asm("{ .reg .u64 t; cvta.to.shared.u64 t, %1; cvt.u32.u64 %0, t; }" : "=r"(a) : "l"(p));
    return a;
}
__device__ __forceinline__ void cp16(uint32_t dst, const void* src) {
    asm volatile("cp.async.cg.shared.global [%0], [%1], 16;" :: "r"(dst), "l"(src) : "memory");
}
__device__ __forceinline__ void cp_commit() {
    asm volatile("cp.async.commit_group;" ::: "memory");
}
template <int N>
__device__ __forceinline__ void cp_wait() {
    asm volatile("cp.async.wait_group %0;" :: "n"(N) : "memory");
}
__device__ __forceinline__ void mma8(float* d, const uint32_t* a, uint32_t b0, uint32_t b1) {
    asm("mma.sync.aligned.m16n8k8.row.col.f32.tf32.tf32.f32 "
        "{%0,%1,%2,%3}, {%4,%5,%6,%7}, {%8,%9}, {%0,%1,%2,%3};"
        : "+f"(d[0]), "+f"(d[1]), "+f"(d[2]), "+f"(d[3])
        : "r"(a[0]), "r"(a[1]), "r"(a[2]), "r"(a[3]), "r"(b0), "r"(b1));
}

// ---------------------------------------------------------------------------
// cvt_pack: blocks [0,384): v1 -> g_v1p4 (interleaved uint4).
//           blocks [384,672): lin_W -> g_lwp (uint2 pairs). Zeroes cbar.
// ---------------------------------------------------------------------------
__global__ __launch_bounds__(256)
void cvt_pack_kernel(const float* __restrict__ v1, const float* __restrict__ linW) {
    const int bid = blockIdx.x, tid = threadIdx.x;
    if (bid < 384) {
        const int idx = bid * 256 + tid;
        const int rb = idx / A4_CNT, rem = idx - rb * A4_CNT;
        const int ks = rem >> 6, p = (rem >> 2) & 15, t4 = rem & 3;
        const int r = rb * 32 + (p & 7) + ((p >> 3) << 4);
        const int k0 = ks * 8 + t4;
        const float* s0 = v1 + r * DIMN + k0;
        const float* s1 = s0 + 8 * DIMN;
        g_v1p4[idx] = make_uint4(f2tf32(s0[0]), f2tf32(s0[4]),
                                 f2tf32(s1[0]), f2tf32(s1[4]));
        if (idx < DIMN) g_cbar[idx] = 0.f;
    } else {
        const int idx = (bid - 384) * 256 + tid;
        const int row = idx / NP, s = idx - row * NP;
        const int k0 = (s >> 2) * 8 + (s & 3);
        const float* src = linW + row * DIMN + k0;
        g_lwp[idx] = make_uint2(f2tf32(src[0]), f2tf32(src[4]));
    }
}

// ---------------------------------------------------------------------------
// prep: per 32x32 tile: p = prod(1-W_k), c = chain bias.
// g_Ptp[j][pairs over i] = rw[i]*p (transposed+packed); cbar[j] += rw[i]*c.
// ---------------------------------------------------------------------------
__global__ __launch_bounds__(256)
void prep_kernel(const float* __restrict__ W, const float* __restrict__ Bb,
                 const float* __restrict__ rw, int nblocks) {
    __shared__ float pt[32][33];
    __shared__ float cp[32][33];
    const int tid = threadIdx.x;
    const int bi = blockIdx.x, bj = blockIdx.y;
    const int il = tid >> 3, j4 = (tid & 7) * 4;
    const int gi = bi * 32 + il, gj = bj * 32 + j4;

    float4 p = make_float4(1.f, 1.f, 1.f, 1.f);
    float4 c = make_float4(0.f, 0.f, 0.f, 0.f);
    for (int k = 0; k < nblocks; k++) {
        float4 w = *(const float4*)&W[(size_t)k * DIMN * DIMN + gi * DIMN + gj];
        float4 b = *(const float4*)&Bb[(size_t)k * DIMN * DIMN + gi * DIMN + gj];
        float4 om = make_float4(1.f - w.x, 1.f - w.y, 1.f - w.z, 1.f - w.w);
        p.x *= om.x; p.y *= om.y; p.z *= om.z; p.w *= om.w;
        c.x = c.x * om.x + b.x; c.y = c.y * om.y + b.y;
        c.z = c.z * om.z + b.z; c.w = c.w * om.w + b.w;
    }
    const float ri = rw[gi];
    pt[il][j4] = ri * p.x; pt[il][j4 + 1] = ri * p.y;
    pt[il][j4 + 2] = ri * p.z; pt[il][j4 + 3] = ri * p.w;
    cp[il][j4] = ri * c.x; cp[il][j4 + 1] = ri * c.y;
    cp[il][j4 + 2] = ri * c.z; cp[il][j4 + 3] = ri * c.w;
    __syncthreads();

    if (tid < 32) {
        float s = 0.f;
#pragma unroll
        for (int i = 0; i < 32; i++) s += cp[i][tid];
        atomicAdd(&g_cbar[bj * 32 + tid], s);
    }
#pragma unroll
    for (int q = tid; q < 512; q += 256) {
        int j = q >> 4, s = q & 15;
        int i0 = (s >> 2) * 8 + (s & 3);
        g_Ptp[(bj * 32 + j) * NP + bi * 16 + s] =
            make_uint2(f2tf32(pt[i0][j]), f2tf32(pt[i0 + 4][j]));
    }
}

// ---------------------------------------------------------------------------
// tf32 mma.sync GEMM, 32x32 tile / CTA, 256 thr / 8 warps = wn(2) x kh(4).
// K = 4 chunks of 96, 2-stage cp.async ring: chunk c+1 loads overlap chunk c
// compute. Per chunk each kh-warp does 3 ks-steps (2 LDS.128 + 2 LDS.64 ->
// 4 MMA each). Cross-quarter reduction via smem.
// MODE 0: t = v2 .* (v1 @ rwP) - cbar   (out: g_tp4, interleaved packed)
// MODE 1: out = (t @ linW^T) + linb     (out: f32 d_out)
// ---------------------------------------------------------------------------
template <int MODE>
__global__ __launch_bounds__(256, 4)
void mma_gemm(const uint4* __restrict__ Ap4, const uint2* __restrict__ Bp,
              const float* __restrict__ v2, const float* __restrict__ cbar,
              const float* __restrict__ linb, void* __restrict__ OutV) {
    extern __shared__ __align__(16) char smc[];

    const int tid = threadIdx.x, lane = tid & 31, wid = tid >> 5;
    const int g = lane >> 2, t4 = lane & 3;
    const int wn = wid & 1, kh = wid >> 1;
    const int rb = blockIdx.y;
    const int m0 = rb * 32, n0 = blockIdx.x * 32;

    const uint32_t sbase = smem_u32(smc);
    const char* aSrc = (const char*)(Ap4 + (size_t)rb * A4_CNT);
    const int brow = tid >> 3, bc0 = tid & 7;
    const char* bSrc = (const char*)(Bp + (size_t)(n0 + brow) * NP);

    // load chunk c into ring buffer buf (all 256 threads; 6 cp16 each)
    auto loadChunk = [&](int c, int buf) {
        const uint32_t aB = sbase + buf * STAGE_B;
        const char* aS = aSrc + c * ABYTES_C;
#pragma unroll
        for (int j = 0; j < 3; j++) {
            int off = (tid + j * 256) * 16;
            cp16(aB + off, aS + off);
        }
        const uint32_t bB = sbase + buf * STAGE_B + ABYTES_C + brow * (PSB * 8);
        const char* bS = bSrc + c * 48 * 8;     // 48 uint2 per chunk row
#pragma unroll
        for (int j = 0; j < 3; j++) {
            int off = (bc0 + 8 * j) * 16;
            cp16(bB + off, bS + off);
        }
        cp_commit();
    };

    float acc[2][2][4] = {};

    loadChunk(0, 0);
    loadChunk(1, 1);

#pragma unroll
    for (int c = 0; c < 4; c++) {
        if (c < 3) cp_wait<1>(); else cp_wait<0>();
        __syncthreads();                 // chunk c visible to all threads

        const int buf = c & 1;
        const uint4* A4b = (const uint4*)(smc + buf * STAGE_B);
        const uint2* Bsb = (const uint2*)(smc + buf * STAGE_B + ABYTES_C);
        const uint4* aP = &A4b[kh * 3 * 64 + g * 4 + t4];        // +64/l, +32 mi
        const uint2* bP = &Bsb[(wn * 16 + g) * PSB + kh * 12 + t4]; // +4/l, +8*PSB nf
#pragma unroll
        for (int l = 0; l < 3; l++) {
            uint4 qa0 = aP[l * 64], qa1 = aP[l * 64 + 32];
            uint2 qb0 = bP[l * 4],  qb1 = bP[8 * PSB + l * 4];
            uint32_t a0[4] = {qa0.x, qa0.z, qa0.y, qa0.w};
            uint32_t a1[4] = {qa1.x, qa1.z, qa1.y, qa1.w};
            mma8(acc[0][0], a0, qb0.x, qb0.y);
            mma8(acc[0][1], a0, qb1.x, qb1.y);
            mma8(acc[1][0], a1, qb0.x, qb0.y);
            mma8(acc[1][1], a1, qb1.x, qb1.y);
        }
        __syncthreads();                 // all reads done before ring reuse
        if (c < 2) loadChunk(c + 2, buf);
    }

    // ---- cross-quarter reduction via smem (reuse ring region) ----
    float* red = (float*)smc;            // 3 buffers of 32x34 floats (13KB)
    if (kh > 0) {
        float* r = red + (kh - 1) * (32 * 34);
#pragma unroll
        for (int mi = 0; mi < 2; mi++) {
            const int rl = mi * 16 + g;
#pragma unroll
            for (int nf = 0; nf < 2; nf++) {
                const int cc = wn * 16 + nf * 8 + 2 * t4;
                *(float2*)&r[rl * 34 + cc]       = make_float2(acc[mi][nf][0], acc[mi][nf][1]);
                *(float2*)&r[(rl + 8) * 34 + cc] = make_float2(acc[mi][nf][2], acc[mi][nf][3]);
            }
        }
    }
    __syncthreads();
    if (kh > 0) return;

#pragma unroll
    for (int b = 0; b < 3; b++) {
        const float* r = red + b * (32 * 34);
#pragma unroll
        for (int mi = 0; mi < 2; mi++) {
            const int rl = mi * 16 + g;
#pragma unroll
            for (int nf = 0; nf < 2; nf++) {
                const int cc = wn * 16 + nf * 8 + 2 * t4;
                float2 p0 = *(const float2*)&r[rl * 34 + cc];
                float2 p1 = *(const float2*)&r[(rl + 8) * 34 + cc];
                acc[mi][nf][0] += p0.x; acc[mi][nf][1] += p0.y;
                acc[mi][nf][2] += p1.x; acc[mi][nf][3] += p1.y;
            }
        }
    }

    // ---- epilogue (kh==0 warps: wn 0,1 cover all 32 cols) ----
#pragma unroll
    for (int mi = 0; mi < 2; mi++) {
        const int r0 = m0 + mi * 16 + g, r1 = r0 + 8;
#pragma unroll
        for (int nf = 0; nf < 2; nf++) {
            const int C = n0 + wn * 16 + nf * 8 + 2 * t4;
            if (MODE == 0) {
                float2 cb = *(const float2*)&cbar[C];
                float2 va = *(const float2*)&v2[r0 * DIMN + C];
                float2 vb = *(const float2*)&v2[r1 * DIMN + C];
                float c0 = va.x * acc[mi][nf][0] - cb.x;
                float c1 = va.y * acc[mi][nf][1] - cb.y;
                float c2 = vb.x * acc[mi][nf][2] - cb.x;
                float c3 = vb.y * acc[mi][nf][3] - cb.y;
                float u0 = __shfl_down_sync(0xffffffffu, c0, 2);
                float u1 = __shfl_down_sync(0xffffffffu, c1, 2);
                float u2 = __shfl_down_sync(0xffffffffu, c2, 2);
                float u3 = __shfl_down_sync(0xffffffffu, c3, 2);
                if (t4 < 2) {
                    const int p = mi * 8 + g;
                    const int ks_g = (n0 + wn * 16 + nf * 8) >> 3;
                    size_t base = (size_t)rb * A4_CNT + ks_g * 64 + p * 4;
                    g_tp4[base + 2 * t4] =
                        make_uint4(f2tf32(c0), f2tf32(u0), f2tf32(c2), f2tf32(u2));
                    g_tp4[base + 2 * t4 + 1] =
                        make_uint4(f2tf32(c1), f2tf32(u1), f2tf32(c3), f2tf32(u3));
                }
            } else {
                float* Out = (float*)OutV;
                float2 lb = *(const float2*)&linb[C];
                *(float2*)&Out[r0 * DIMN + C] =
                    make_float2(acc[mi][nf][0] + lb.x, acc[mi][nf][1] + lb.y);
                *(float2*)&Out[r1 * DIMN + C] =
                    make_float2(acc[mi][nf][2] + lb.x, acc[mi][nf][3] + lb.y);
            }
        }
    }
}

// ---------------------------------------------------------------------------
// Launch. Inputs: v1, v2, block_W, block_b, row_weights, lin_W, lin_b
// ---------------------------------------------------------------------------
extern "C" void kernel_launch(void* const* d_in, const int* in_sizes, int n_in,
                              void* d_out, int out_size) {
    const float* v1   = (const float*)d_in[0];
    const float* v2   = (const float*)d_in[1];
    const float* bW   = (const float*)d_in[2];
    const float* bB   = (const float*)d_in[3];
    const float* rw   = (const float*)d_in[4];
    const float* linW = (const float*)d_in[5];
    const float* linb = (const float*)d_in[6];

    const int nblocks = in_sizes[2] / (DIMN * DIMN);
    const int batch   = in_sizes[0] / DIMN;

    uint4 *gv1p4, *gtp4; uint2 *glwp, *gPtp; float* gcb;
    cudaGetSymbolAddress((void**)&gv1p4, g_v1p4);
    cudaGetSymbolAddress((void**)&gtp4,  g_tp4);
    cudaGetSymbolAddress((void**)&glwp,  g_lwp);
    cudaGetSymbolAddress((void**)&gPtp,  g_Ptp);
    cudaGetSymbolAddress((void**)&gcb,   g_cbar);

    cudaFuncSetAttribute(mma_gemm<0>, cudaFuncAttributeMaxDynamicSharedMemorySize, SMEM_GEMM);
    cudaFuncSetAttribute(mma_gemm<1>, cudaFuncAttributeMaxDynamicSharedMemorySize, SMEM_GEMM);

    cvt_pack_kernel<<<672, 256>>>(v1, linW);
    prep_kernel<<<dim3(12, 12), 256>>>(bW, bB, rw, nblocks);
    dim3 grid(DIMN / 32, batch / 32);   // (12, 32) = 384 CTAs
    mma_gemm<0><<<grid, 256, SMEM_GEMM>>>(gv1p4, gPtp, v2, gcb, nullptr, nullptr);
    mma_gemm<1><<<grid, 256, SMEM_GEMM>>>(gtp4, glwp, nullptr, nullptr, linb, d_out);
}